// round 11
// baseline (speedup 1.0000x reference)
#include <cuda_runtime.h>
#include <math.h>

// Problem constants
#define HH 256
#define WW 256
#define HWP (HH*WW)   // 65536

// ---------------- scratch (no allocations allowed) ----------------
__device__ __align__(16) float g_bufA[2 * 64 * HWP];
__device__ __align__(16) float g_bufB[2 * 64 * HWP];
__device__ __align__(16) float g_raw [2 * 216 * HWP];
__device__ __align__(16) float g_featT[2 * 64 * HWP];   // [br][g][pix][8]
__device__ __align__(16) float g_fpn [128 * HWP];       // cat(fp, fn)
__device__ __align__(16) float g_wre [2 * 8 * 9 * 8 * 64]; // [br][g][k][c][o]

// ---------------- packed fp32x2 helpers (Blackwell FFMA2) ----------------
typedef unsigned long long u64;

__device__ __forceinline__ u64 pk2(float a, float b) {
    u64 r; asm("mov.b64 %0, {%1, %2};" : "=l"(r) : "f"(a), "f"(b)); return r;
}
__device__ __forceinline__ float2 upk2(u64 a) {
    float2 r; asm("mov.b64 {%0, %1}, %2;" : "=f"(r.x), "=f"(r.y) : "l"(a)); return r;
}
__device__ __forceinline__ u64 ffma2(u64 a, u64 b, u64 c) {
    u64 d; asm("fma.rn.f32x2 %0, %1, %2, %3;" : "=l"(d) : "l"(a), "l"(b), "l"(c)); return d;
}

// cp.async 4B with zero-fill on invalid
__device__ __forceinline__ void cp4(unsigned int dst, const void* src, int sz) {
    asm volatile("cp.async.ca.shared.global [%0], [%1], 4, %2;"
                 :: "r"(dst), "l"(src), "r"(sz));
}
__device__ __forceinline__ void cp_commit() {
    asm volatile("cp.async.commit_group;");
}

// ---------------- direct 3x3 conv, pad 1, NCHW, branch-batched ----------------
// 32x32 pixel tile; 256 threads (32,8); each thread: 4 pixel rows x 16 out
// channels (channel pair in f32x2 lanes). Double-buffered cp.async over Cin
// (4 channels/stage), interior/halo split (no stored descriptors).
// act: 0 = none, 1 = leaky relu, 2 = offset/mask activation (+flow).
#define CO_T 16
#define PY 4
#define CI_ELEMS (34*34)        // 1156
#define TILE_ELEMS (4*34*34)    // 4624
#define W_ELEMS (4*9*CO_T)      // 576

__global__ __launch_bounds__(256, 3)
void conv3x3_kernel(const float* __restrict__ in0, const float* __restrict__ in1,
                    const float* __restrict__ wt0, const float* __restrict__ wt1,
                    const float* __restrict__ bs0, const float* __restrict__ bs1,
                    float* __restrict__ out0, float* __restrict__ out1,
                    int Cin, int Cout, int zPerBr, int act,
                    const float* __restrict__ flow0, const float* __restrict__ flow1)
{
    __shared__ __align__(16) float s_in[2][TILE_ELEMS];
    __shared__ __align__(16) float s_w[2][W_ELEMS];

    const int tx = threadIdx.x, ty = threadIdx.y;   // (32,8)
    const int tid = ty * 32 + tx;
    const int br  = blockIdx.z / zPerBr;
    const int coz = blockIdx.z - br * zPerBr;
    const int x0p = blockIdx.x * 32, y0p = blockIdx.y * 32;
    const int co0 = coz * CO_T;

    const float* in   = br ? in1 : in0;
    const float* wt   = br ? wt1 : wt0;
    const float* bias = br ? bs1 : bs0;
    float*       out  = br ? out1 : out0;
    const float* flow = br ? flow1 : flow0;

    const unsigned int s_in_base = (unsigned int)__cvta_generic_to_shared(&s_in[0][0]);
    const int nIter = Cin >> 2;

    // ---- input stage: interior (in-bounds by construction) + halo ----
    auto issue = [&](int it, int buf) {
        const float* inb = in + (size_t)(it * 4) * HWP;
        unsigned int sb = s_in_base + (unsigned)buf * (TILE_ELEMS * 4);
#pragma unroll
        for (int ci = 0; ci < 4; ci++) {
            const float* cb = inb + (size_t)ci * HWP;
            unsigned int scb = sb + (unsigned)(ci * CI_ELEMS) * 4;
            // interior: thread -> pixel (r, c), 4 rows apart by 8
            const int r = tid >> 5, c = tid & 31;
#pragma unroll
            for (int j = 0; j < 4; j++) {
                int rr = r + 8 * j;
                cp4(scb + (unsigned)((rr + 1) * 34 + (c + 1)) * 4,
                    cb + (y0p + rr) * WW + (x0p + c), 4);
            }
            // halo: 132 elements
            if (tid < 132) {
                int sidx, gy, gx;
                if (tid < 34)       { sidx = tid;               gy = y0p - 1;          gx = x0p + tid - 1; }
                else if (tid < 68)  { sidx = 33 * 34 + tid - 34; gy = y0p + 32;        gx = x0p + tid - 35; }
                else if (tid < 100) { int q = tid - 68;  sidx = (q + 1) * 34;      gy = y0p + q; gx = x0p - 1; }
                else                { int q = tid - 100; sidx = (q + 1) * 34 + 33; gy = y0p + q; gx = x0p + 32; }
                bool ok = (gy >= 0 && gy < HH && gx >= 0 && gx < WW);
                cp4(scb + (unsigned)sidx * 4, ok ? (const void*)(cb + gy * WW + gx) : (const void*)cb, ok ? 4 : 0);
            }
        }
        cp_commit();
    };
    // weight fetch (recomputed decode, no stored indices)
    auto wldg = [&](int it, float* v) {
#pragma unroll
        for (int j = 0; j < 3; j++) {
            int idx = tid + j * 256;
            if (idx < W_ELEMS) {
                int co = idx & 15, t = idx >> 4;
                int k = t % 9, ci = t / 9;
                v[j] = __ldg(&wt[((size_t)(co0 + co) * Cin + it * 4 + ci) * 9 + k]);
            }
        }
    };
    auto wsts = [&](int buf, const float* v) {
#pragma unroll
        for (int j = 0; j < 3; j++) {
            int idx = tid + j * 256;
            if (idx < W_ELEMS) s_w[buf][idx] = v[j];
        }
    };

    u64 acc2[PY][CO_T / 2];
#pragma unroll
    for (int p = 0; p < PY; p++)
#pragma unroll
        for (int i = 0; i < CO_T / 2; i++) acc2[p][i] = 0ull;

    // prologue
    issue(0, 0);
    { float v[3]; wldg(0, v); wsts(0, v); }

#pragma unroll 1
    for (int it = 0; it < nIter; it++) {
        const int buf = it & 1;
        float wv[3];
        if (it + 1 < nIter) wldg(it + 1, wv);      // overlap LDG with wait
        asm volatile("cp.async.wait_group 0;");
        __syncthreads();
        if (it + 1 < nIter) {
            wsts(buf ^ 1, wv);
            issue(it + 1, buf ^ 1);                // after sync: buf^1 free
        }

        const float* si = &s_in[buf][0];
        const float* sw = &s_w[buf][0];
#pragma unroll 1
        for (int ci = 0; ci < 4; ci++) {
#pragma unroll
            for (int k = 0; k < 9; k++) {
                const int dy = k / 3, dx = k - 3 * (k / 3);
                const ulonglong2* wv2 = (const ulonglong2*)&sw[ci * 144 + k * 16];
                ulonglong2 w01 = wv2[0], w23 = wv2[1];
                ulonglong2 w45 = wv2[2], w67 = wv2[3];
#pragma unroll
                for (int p = 0; p < PY; p++) {
                    float vv = si[ci * CI_ELEMS + (ty + 8 * p + dy) * 34 + (tx + dx)];
                    u64 vp = pk2(vv, vv);
                    acc2[p][0] = ffma2(w01.x, vp, acc2[p][0]);
                    acc2[p][1] = ffma2(w01.y, vp, acc2[p][1]);
                    acc2[p][2] = ffma2(w23.x, vp, acc2[p][2]);
                    acc2[p][3] = ffma2(w23.y, vp, acc2[p][3]);
                    acc2[p][4] = ffma2(w45.x, vp, acc2[p][4]);
                    acc2[p][5] = ffma2(w45.y, vp, acc2[p][5]);
                    acc2[p][6] = ffma2(w67.x, vp, acc2[p][6]);
                    acc2[p][7] = ffma2(w67.y, vp, acc2[p][7]);
                }
            }
        }
        __syncthreads();
    }

    const int x = x0p + tx;
#pragma unroll
    for (int p = 0; p < PY; p++) {
        const int y = y0p + ty + 8 * p;
        const int pix = y * WW + x;
#pragma unroll
        for (int i = 0; i < CO_T / 2; i++) {
            float2 v2 = upk2(acc2[p][i]);
#pragma unroll
            for (int h = 0; h < 2; h++) {
                int co = co0 + 2 * i + h;
                if (co < Cout) {
                    float r = ((h == 0) ? v2.x : v2.y) + bias[co];
                    if (act == 1) {
                        r = (r >= 0.f) ? r : 0.1f * r;
                    } else if (act == 2) {
                        if (co < 144) {
                            float f = flow[(size_t)((co & 1) ^ 1) * HWP + pix];
                            r = 10.f * tanhf(r) + f;
                        } else {
                            r = 1.f / (1.f + expf(-r));
                        }
                    }
                    out[(size_t)co * HWP + pix] = r;
                }
            }
        }
    }
}

// ---------------- feat NCHW -> [br][g][pix][8] ----------------
__global__ void transpose_kernel(const float* __restrict__ f0, const float* __restrict__ f1,
                                 float* __restrict__ featT)
{
    int pix = blockIdx.x * blockDim.x + threadIdx.x;
    int g = blockIdx.y;
    int br = blockIdx.z;
    if (pix >= HWP) return;
    const float* feat = br ? f1 : f0;
    const float* base = feat + (size_t)g * 8 * HWP + pix;
    float4 a, b;
    a.x = base[0 * HWP]; a.y = base[1 * HWP]; a.z = base[2 * HWP]; a.w = base[3 * HWP];
    b.x = base[4 * HWP]; b.y = base[5 * HWP]; b.z = base[6 * HWP]; b.w = base[7 * HWP];
    float4* dst = (float4*)(featT + (size_t)br * 64 * HWP + ((size_t)g * HWP + pix) * 8);
    dst[0] = a; dst[1] = b;
}

// ---------------- dcn weight reorder: w[o][g*8+c][k] -> wre[br][g][k][c][o] ----------------
__global__ void wreorder_kernel(const float* __restrict__ w0, const float* __restrict__ w1,
                                float* __restrict__ wre)
{
    int i = blockIdx.x * blockDim.x + threadIdx.x;
    if (i >= 2 * 36864) return;
    int br = i >= 36864;
    int l = i - br * 36864;
    const float* w = br ? w1 : w0;
    int o  = l & 63;
    int t  = l >> 6;
    int c  = t & 7;
    int gk = t >> 3;
    int k = gk % 9;
    int g = gk / 9;
    wre[i] = w[((size_t)o * 64 + g * 8 + c) * 9 + k];
}

// ---------------- modulated deformable conv (fp32x2 accumulation) ----------------
__device__ __forceinline__ void mdcn_corner(const float* __restrict__ fb,
                                            int iy, int ix, float wgt, u64* s2)
{
    if (iy >= 0 && iy < HH && ix >= 0 && ix < WW) {
        const ulonglong2* p = (const ulonglong2*)(fb + ((size_t)iy * WW + ix) * 8);
        ulonglong2 a = p[0], b = p[1];
        u64 wp = pk2(wgt, wgt);
        s2[0] = ffma2(a.x, wp, s2[0]);
        s2[1] = ffma2(a.y, wp, s2[1]);
        s2[2] = ffma2(b.x, wp, s2[2]);
        s2[3] = ffma2(b.y, wp, s2[3]);
    }
}

__global__ __launch_bounds__(256)
void mdcn_kernel(const float* __restrict__ featT_all, const float* __restrict__ off_all,
                 const float* __restrict__ wre_all,
                 const float* __restrict__ bias0, const float* __restrict__ bias1,
                 float* __restrict__ out_all)
{
    __shared__ __align__(16) float sw[9 * 8 * 64];   // [k][c][o] for current g

    const int tx = threadIdx.x, ty = threadIdx.y;
    const int tid = ty * 32 + tx;
    const int br = blockIdx.z;
    const int x = blockIdx.x * 32 + tx, y = blockIdx.y * 8 + ty;
    const int pix = y * WW + x;

    const float* featT = featT_all + (size_t)br * 64 * HWP;
    const float* off   = off_all   + (size_t)br * 216 * HWP;
    const float* wre   = wre_all   + (size_t)br * 36864;
    const float* bias  = br ? bias1 : bias0;
    float*       out   = out_all   + (size_t)br * 64 * HWP;

    u64 acc2[32];
#pragma unroll
    for (int i = 0; i < 32; i++) acc2[i] = 0ull;

#pragma unroll 1
    for (int g = 0; g < 8; g++) {
        __syncthreads();
        for (int i = tid; i < 4608; i += 256) sw[i] = wre[g * 4608 + i];
        __syncthreads();

        const float* fb = featT + (size_t)g * HWP * 8;
#pragma unroll 1
        for (int k = 0; k < 9; k++) {
            int ch = g * 9 + k;
            float oy = off[(size_t)(2 * ch) * HWP + pix];
            float ox = off[(size_t)(2 * ch + 1) * HWP + pix];
            float m  = off[(size_t)(144 + ch) * HWP + pix];
            float py = (float)(y + (k / 3) - 1) + oy;
            float px = (float)(x + (k % 3) - 1) + ox;
            float y0f = floorf(py), x0f = floorf(px);
            float ly = py - y0f, lx = px - x0f;
            int iy = (int)y0f, ix = (int)x0f;

            u64 s2[4];
#pragma unroll
            for (int c = 0; c < 4; c++) s2[c] = 0ull;
            float w00 = (1.f - ly) * (1.f - lx);
            float w01 = (1.f - ly) * lx;
            float w10 = ly * (1.f - lx);
            float w11 = ly * lx;
            mdcn_corner(fb, iy,     ix,     w00, s2);
            mdcn_corner(fb, iy,     ix + 1, w01, s2);
            mdcn_corner(fb, iy + 1, ix,     w10, s2);
            mdcn_corner(fb, iy + 1, ix + 1, w11, s2);

            float s[8];
#pragma unroll
            for (int c = 0; c < 4; c++) {
                float2 v2 = upk2(s2[c]);
                s[2 * c] = v2.x; s[2 * c + 1] = v2.y;
            }

#pragma unroll
            for (int c = 0; c < 8; c++) {
                float sc = s[c] * m;
                u64 scp = pk2(sc, sc);
                const ulonglong2* wp = (const ulonglong2*)&sw[(k * 8 + c) * 64];
#pragma unroll
                for (int j = 0; j < 16; j++) {
                    ulonglong2 wv = wp[j];
                    acc2[2 * j    ] = ffma2(wv.x, scp, acc2[2 * j    ]);
                    acc2[2 * j + 1] = ffma2(wv.y, scp, acc2[2 * j + 1]);
                }
            }
        }
    }

#pragma unroll
    for (int i = 0; i < 32; i++) {
        float2 v2 = upk2(acc2[i]);
        out[(size_t)(2 * i    ) * HWP + pix] = v2.x + bias[2 * i    ];
        out[(size_t)(2 * i + 1) * HWP + pix] = v2.y + bias[2 * i + 1];
    }
}

// ---------------- launch ----------------
extern "C" void kernel_launch(void* const* d_in, const int* in_sizes, int n_in,
                              void* d_out, int out_size)
{
    (void)in_sizes; (void)n_in; (void)out_size;
    const float* feat_prev  = (const float*)d_in[0];
    const float* feat_next  = (const float*)d_in[1];
    const float* extra_prev = (const float*)d_in[2];
    const float* extra_next = (const float*)d_in[3];
    const float* flow_prev  = (const float*)d_in[4];
    const float* flow_next  = (const float*)d_in[5];
    const float* off_w[2][4];
    const float* off_b[2][4];
    for (int br = 0; br < 2; br++)
        for (int j = 0; j < 4; j++) {
            off_w[br][j] = (const float*)d_in[6 + br * 8 + 2 * j];
            off_b[br][j] = (const float*)d_in[6 + br * 8 + 2 * j + 1];
        }
    const float* dcn_w[2] = {(const float*)d_in[22], (const float*)d_in[24]};
    const float* dcn_b[2] = {(const float*)d_in[23], (const float*)d_in[25]};
    const float* fus_w = (const float*)d_in[26];
    const float* fus_b = (const float*)d_in[27];
    float* out = (float*)d_out;

    float *bufA, *bufB, *raw, *featT, *fpn, *wre;
    cudaGetSymbolAddress((void**)&bufA,  g_bufA);
    cudaGetSymbolAddress((void**)&bufB,  g_bufB);
    cudaGetSymbolAddress((void**)&raw,   g_raw);
    cudaGetSymbolAddress((void**)&featT, g_featT);
    cudaGetSymbolAddress((void**)&fpn,   g_fpn);
    cudaGetSymbolAddress((void**)&wre,   g_wre);

    float* bufA1 = bufA + (size_t)64 * HWP;
    float* bufB1 = bufB + (size_t)64 * HWP;
    float* raw1  = raw  + (size_t)216 * HWP;

    const dim3 cb(32, 8);
    const dim3 cgB64 (WW / 32, HH / 32, 8);    // 2 branches x 4 chunks of 16
    const dim3 cgB216(WW / 32, HH / 32, 28);   // 2 branches x 14 chunks of 16
    const dim3 cgFus (WW / 32, HH / 32, 4);    // fusion: 1 "branch", 4 chunks
    const dim3 mg(WW / 32, HH / 8, 2);

    // conv stage 0..2 (leaky relu), both branches batched
    conv3x3_kernel<<<cgB64, cb>>>(extra_prev, extra_next,
                                  off_w[0][0], off_w[1][0], off_b[0][0], off_b[1][0],
                                  bufA, bufA1, 128, 64, 4, 1, nullptr, nullptr);
    conv3x3_kernel<<<cgB64, cb>>>(bufA, bufA1,
                                  off_w[0][1], off_w[1][1], off_b[0][1], off_b[1][1],
                                  bufB, bufB1, 64, 64, 4, 1, nullptr, nullptr);
    conv3x3_kernel<<<cgB64, cb>>>(bufB, bufB1,
                                  off_w[0][2], off_w[1][2], off_b[0][2], off_b[1][2],
                                  bufA, bufA1, 64, 64, 4, 1, nullptr, nullptr);
    // conv216 with fused offset/mask activation (+flow add)
    conv3x3_kernel<<<cgB216, cb>>>(bufA, bufA1,
                                   off_w[0][3], off_w[1][3], off_b[0][3], off_b[1][3],
                                   raw, raw1, 64, 216, 14, 2, flow_prev, flow_next);
    // feature transpose + dcn weight reorder
    transpose_kernel<<<dim3(HWP / 256, 8, 2), 256>>>(feat_prev, feat_next, featT);
    wreorder_kernel<<<288, 256>>>(dcn_w[0], dcn_w[1], wre);
    // deformable conv, both branches batched
    mdcn_kernel<<<mg, cb>>>(featT, raw, wre, dcn_b[0], dcn_b[1], fpn);
    // fusion conv
    conv3x3_kernel<<<cgFus, cb>>>(fpn, fpn, fus_w, fus_w, fus_b, fus_b,
                                  out, out, 128, 64, 4, 0, nullptr, nullptr);
}

// round 14
// speedup vs baseline: 1.3603x; 1.3603x over previous
#include <cuda_runtime.h>
#include <math.h>

// Problem constants
#define HH 256
#define WW 256
#define HWP (HH*WW)   // 65536

// ---------------- scratch (no allocations allowed) ----------------
__device__ __align__(16) float g_bufA[2 * 64 * HWP];
__device__ __align__(16) float g_bufB[2 * 64 * HWP];
__device__ __align__(16) float g_raw [2 * 216 * HWP];
__device__ __align__(16) float g_featT[2 * 64 * HWP];   // [br][g][pix][8]
__device__ __align__(16) float g_fpn [128 * HWP];       // cat(fp, fn)
__device__ __align__(16) float g_wre [2 * 8 * 9 * 8 * 64]; // [br][g][k][c][o]

// ---------------- packed fp32x2 helpers (Blackwell FFMA2) ----------------
typedef unsigned long long u64;

__device__ __forceinline__ u64 pk2(float a, float b) {
    u64 r; asm("mov.b64 %0, {%1, %2};" : "=l"(r) : "f"(a), "f"(b)); return r;
}
__device__ __forceinline__ float2 upk2(u64 a) {
    float2 r; asm("mov.b64 {%0, %1}, %2;" : "=f"(r.x), "=f"(r.y) : "l"(a)); return r;
}
__device__ __forceinline__ u64 ffma2(u64 a, u64 b, u64 c) {
    u64 d; asm("fma.rn.f32x2 %0, %1, %2, %3;" : "=l"(d) : "l"(a), "l"(b), "l"(c)); return d;
}

// cp.async 4B with zero-fill on invalid
__device__ __forceinline__ void cp4(unsigned int dst, const void* src, int sz) {
    asm volatile("cp.async.ca.shared.global [%0], [%1], 4, %2;"
                 :: "r"(dst), "l"(src), "r"(sz));
}
__device__ __forceinline__ void cp_commit() {
    asm volatile("cp.async.commit_group;");
}

// ---------------- direct 3x3 conv, pad 1, NCHW, branch-batched ----------------
// 32x32 pixel tile; 256 threads (32,8). f32x2 lanes hold an INPUT-CHANNEL PAIR:
// smem input tile stored as u64 per pixel per ci-pair; weights as float4 (4 Cin
// taps) per (k, co) -> one broadcast LDS.128 feeds 2 FFMA2. Each thread: 4 pixel
// rows x 8 output channels. Accumulators hold (even-ci, odd-ci) partial sums,
// combined once in the epilogue (exact fp32).
// act: 0 = none, 1 = leaky relu, 2 = offset/mask activation (+flow).
#define CO_T 8
#define PY 4
#define CI_ELEMS (34*34)        // 1156
#define W_FLOATS 288            // 9k * 8co * 4ci

__global__ __launch_bounds__(256, 2)
void conv3x3_kernel(const float* __restrict__ in0, const float* __restrict__ in1,
                    const float* __restrict__ wt0, const float* __restrict__ wt1,
                    const float* __restrict__ bs0, const float* __restrict__ bs1,
                    float* __restrict__ out0, float* __restrict__ out1,
                    int Cin, int Cout, int zPerBr, int act,
                    const float* __restrict__ flow0, const float* __restrict__ flow1)
{
    __shared__ __align__(16) u64   s_in[2][2][CI_ELEMS];  // [buf][cipair][pix]
    __shared__ __align__(16) float s_w[2][W_FLOATS];      // [buf][(k*8+co)*4+ci]

    const int tx = threadIdx.x, ty = threadIdx.y;   // (32,8)
    const int tid = ty * 32 + tx;
    const int br  = blockIdx.z / zPerBr;
    const int coz = blockIdx.z - br * zPerBr;
    const int x0p = blockIdx.x * 32, y0p = blockIdx.y * 32;
    const int co0 = coz * CO_T;

    const float* in   = br ? in1 : in0;
    const float* wt   = br ? wt1 : wt0;
    const float* bias = br ? bs1 : bs0;
    float*       out  = br ? out1 : out0;
    const float* flow = br ? flow1 : flow0;

    const unsigned int s_in_base = (unsigned int)__cvta_generic_to_shared(&s_in[0][0][0]);
    const unsigned int s_w_base  = (unsigned int)__cvta_generic_to_shared(&s_w[0][0]);
    const int nIter = Cin >> 2;

    // ---- stage one Cin-chunk (4 channels) + its weights via cp.async ----
    auto issue = [&](int it, int buf) {
        const float* inb = in + (size_t)(it * 4) * HWP;
#pragma unroll
        for (int ci = 0; ci < 4; ci++) {
            const float* cb = inb + (size_t)ci * HWP;
            // dst: [buf][ci>>1][pix] u64, lane (ci&1) = 4B offset
            unsigned int db = s_in_base + (unsigned)buf * (2 * CI_ELEMS * 8)
                            + (unsigned)(ci >> 1) * (CI_ELEMS * 8) + (unsigned)(ci & 1) * 4;
            const int r = tid >> 5, c = tid & 31;
#pragma unroll
            for (int j = 0; j < 4; j++) {
                int rr = r + 8 * j;
                cp4(db + (unsigned)((rr + 1) * 34 + (c + 1)) * 8,
                    cb + (y0p + rr) * WW + (x0p + c), 4);
            }
            if (tid < 132) {
                int sidx, gy, gx;
                if (tid < 34)       { sidx = tid;                    gy = y0p - 1;  gx = x0p + tid - 1; }
                else if (tid < 68)  { sidx = 33 * 34 + (tid - 34);   gy = y0p + 32; gx = x0p + tid - 35; }
                else if (tid < 100) { int q = tid - 68;  sidx = (q + 1) * 34;      gy = y0p + q; gx = x0p - 1; }
                else                { int q = tid - 100; sidx = (q + 1) * 34 + 33; gy = y0p + q; gx = x0p + 32; }
                bool ok = (gy >= 0 && gy < HH && gx >= 0 && gx < WW);
                cp4(db + (unsigned)sidx * 8, ok ? (const void*)(cb + gy * WW + gx) : (const void*)cb, ok ? 4 : 0);
            }
        }
        // weights: 288 floats, layout (k*8+co)*4+ci
#pragma unroll
        for (int j = 0; j < 2; j++) {
            int idx = tid + j * 256;
            if (idx < W_FLOATS) {
                int ci = idx & 3;
                int co = (idx >> 2) & 7;
                int k  = idx >> 5;
                cp4(s_w_base + (unsigned)buf * (W_FLOATS * 4) + (unsigned)idx * 4,
                    wt + ((size_t)(co0 + co) * Cin + it * 4 + ci) * 9 + k, 4);
            }
        }
        cp_commit();
    };

    u64 acc2[PY][CO_T];   // [p][co] = (even-ci partial, odd-ci partial)
#pragma unroll
    for (int p = 0; p < PY; p++)
#pragma unroll
        for (int i = 0; i < CO_T; i++) acc2[p][i] = 0ull;

    issue(0, 0);

#pragma unroll 1
    for (int it = 0; it < nIter; it++) {
        const int buf = it & 1;
        if (it + 1 < nIter) {
            issue(it + 1, buf ^ 1);
            asm volatile("cp.async.wait_group 1;");
        } else {
            asm volatile("cp.async.wait_group 0;");
        }
        __syncthreads();

        const u64* si0 = &s_in[buf][0][0];
        const u64* si1 = &s_in[buf][1][0];
        const ulonglong2* wq = (const ulonglong2*)&s_w[buf][0];  // entry = (k*8+co)
#pragma unroll
        for (int dy = 0; dy < 3; dy++) {
#pragma unroll
            for (int dx = 0; dx < 3; dx++) {
                const int k = dy * 3 + dx;
                ulonglong2 w[CO_T];
#pragma unroll
                for (int co = 0; co < CO_T; co++) w[co] = wq[k * 8 + co];
#pragma unroll
                for (int p = 0; p < PY; p++) {
                    const int pixk = (ty + 8 * p + dy) * 34 + (tx + dx);
                    u64 a01 = si0[pixk];
                    u64 a23 = si1[pixk];
#pragma unroll
                    for (int co = 0; co < CO_T; co++) {
                        acc2[p][co] = ffma2(w[co].x, a01, acc2[p][co]);
                        acc2[p][co] = ffma2(w[co].y, a23, acc2[p][co]);
                    }
                }
            }
        }
        __syncthreads();
    }

    const int x = x0p + tx;
#pragma unroll
    for (int p = 0; p < PY; p++) {
        const int y = y0p + ty + 8 * p;
        const int pix = y * WW + x;
#pragma unroll
        for (int i = 0; i < CO_T; i++) {
            const int co = co0 + i;
            float2 v2 = upk2(acc2[p][i]);
            float r = v2.x + v2.y + bias[co];
            if (act == 1) {
                r = (r >= 0.f) ? r : 0.1f * r;
            } else if (act == 2) {
                if (co < 144) {
                    float f = flow[(size_t)((co & 1) ^ 1) * HWP + pix];
                    r = 10.f * tanhf(r) + f;
                } else {
                    r = 1.f / (1.f + expf(-r));
                }
            }
            out[(size_t)co * HWP + pix] = r;
        }
    }
}

// ---------------- feat NCHW -> [br][g][pix][8] ----------------
__global__ void transpose_kernel(const float* __restrict__ f0, const float* __restrict__ f1,
                                 float* __restrict__ featT)
{
    int pix = blockIdx.x * blockDim.x + threadIdx.x;
    int g = blockIdx.y;
    int br = blockIdx.z;
    if (pix >= HWP) return;
    const float* feat = br ? f1 : f0;
    const float* base = feat + (size_t)g * 8 * HWP + pix;
    float4 a, b;
    a.x = base[0 * HWP]; a.y = base[1 * HWP]; a.z = base[2 * HWP]; a.w = base[3 * HWP];
    b.x = base[4 * HWP]; b.y = base[5 * HWP]; b.z = base[6 * HWP]; b.w = base[7 * HWP];
    float4* dst = (float4*)(featT + (size_t)br * 64 * HWP + ((size_t)g * HWP + pix) * 8);
    dst[0] = a; dst[1] = b;
}

// ---------------- dcn weight reorder: w[o][g*8+c][k] -> wre[br][g][k][c][o] ----------------
__global__ void wreorder_kernel(const float* __restrict__ w0, const float* __restrict__ w1,
                                float* __restrict__ wre)
{
    int i = blockIdx.x * blockDim.x + threadIdx.x;
    if (i >= 2 * 36864) return;
    int br = i >= 36864;
    int l = i - br * 36864;
    const float* w = br ? w1 : w0;
    int o  = l & 63;
    int t  = l >> 6;
    int c  = t & 7;
    int gk = t >> 3;
    int k = gk % 9;
    int g = gk / 9;
    wre[i] = w[((size_t)o * 64 + g * 8 + c) * 9 + k];
}

// ---------------- modulated deformable conv (fp32x2 accumulation) ----------------
__device__ __forceinline__ void mdcn_corner(const float* __restrict__ fb,
                                            int iy, int ix, float wgt, u64* s2)
{
    if (iy >= 0 && iy < HH && ix >= 0 && ix < WW) {
        const ulonglong2* p = (const ulonglong2*)(fb + ((size_t)iy * WW + ix) * 8);
        ulonglong2 a = p[0], b = p[1];
        u64 wp = pk2(wgt, wgt);
        s2[0] = ffma2(a.x, wp, s2[0]);
        s2[1] = ffma2(a.y, wp, s2[1]);
        s2[2] = ffma2(b.x, wp, s2[2]);
        s2[3] = ffma2(b.y, wp, s2[3]);
    }
}

__global__ __launch_bounds__(256)
void mdcn_kernel(const float* __restrict__ featT_all, const float* __restrict__ off_all,
                 const float* __restrict__ wre_all,
                 const float* __restrict__ bias0, const float* __restrict__ bias1,
                 float* __restrict__ out_all)
{
    __shared__ __align__(16) float sw[9 * 8 * 64];   // [k][c][o] for current g

    const int tx = threadIdx.x, ty = threadIdx.y;
    const int tid = ty * 32 + tx;
    const int br = blockIdx.z;
    const int x = blockIdx.x * 32 + tx, y = blockIdx.y * 8 + ty;
    const int pix = y * WW + x;

    const float* featT = featT_all + (size_t)br * 64 * HWP;
    const float* off   = off_all   + (size_t)br * 216 * HWP;
    const float* wre   = wre_all   + (size_t)br * 36864;
    const float* bias  = br ? bias1 : bias0;
    float*       out   = out_all   + (size_t)br * 64 * HWP;

    u64 acc2[32];
#pragma unroll
    for (int i = 0; i < 32; i++) acc2[i] = 0ull;

#pragma unroll 1
    for (int g = 0; g < 8; g++) {
        __syncthreads();
        for (int i = tid; i < 4608; i += 256) sw[i] = wre[g * 4608 + i];
        __syncthreads();

        const float* fb = featT + (size_t)g * HWP * 8;
#pragma unroll 1
        for (int k = 0; k < 9; k++) {
            int ch = g * 9 + k;
            float oy = off[(size_t)(2 * ch) * HWP + pix];
            float ox = off[(size_t)(2 * ch + 1) * HWP + pix];
            float m  = off[(size_t)(144 + ch) * HWP + pix];
            float py = (float)(y + (k / 3) - 1) + oy;
            float px = (float)(x + (k % 3) - 1) + ox;
            float y0f = floorf(py), x0f = floorf(px);
            float ly = py - y0f, lx = px - x0f;
            int iy = (int)y0f, ix = (int)x0f;

            u64 s2[4];
#pragma unroll
            for (int c = 0; c < 4; c++) s2[c] = 0ull;
            float w00 = (1.f - ly) * (1.f - lx);
            float w01 = (1.f - ly) * lx;
            float w10 = ly * (1.f - lx);
            float w11 = ly * lx;
            mdcn_corner(fb, iy,     ix,     w00, s2);
            mdcn_corner(fb, iy,     ix + 1, w01, s2);
            mdcn_corner(fb, iy + 1, ix,     w10, s2);
            mdcn_corner(fb, iy + 1, ix + 1, w11, s2);

            float s[8];
#pragma unroll
            for (int c = 0; c < 4; c++) {
                float2 v2 = upk2(s2[c]);
                s[2 * c] = v2.x; s[2 * c + 1] = v2.y;
            }

#pragma unroll
            for (int c = 0; c < 8; c++) {
                float sc = s[c] * m;
                u64 scp = pk2(sc, sc);
                const ulonglong2* wp = (const ulonglong2*)&sw[(k * 8 + c) * 64];
#pragma unroll
                for (int j = 0; j < 16; j++) {
                    ulonglong2 wv = wp[j];
                    acc2[2 * j    ] = ffma2(wv.x, scp, acc2[2 * j    ]);
                    acc2[2 * j + 1] = ffma2(wv.y, scp, acc2[2 * j + 1]);
                }
            }
        }
    }

#pragma unroll
    for (int i = 0; i < 32; i++) {
        float2 v2 = upk2(acc2[i]);
        out[(size_t)(2 * i    ) * HWP + pix] = v2.x + bias[2 * i    ];
        out[(size_t)(2 * i + 1) * HWP + pix] = v2.y + bias[2 * i + 1];
    }
}

// ---------------- launch ----------------
extern "C" void kernel_launch(void* const* d_in, const int* in_sizes, int n_in,
                              void* d_out, int out_size)
{
    (void)in_sizes; (void)n_in; (void)out_size;
    const float* feat_prev  = (const float*)d_in[0];
    const float* feat_next  = (const float*)d_in[1];
    const float* extra_prev = (const float*)d_in[2];
    const float* extra_next = (const float*)d_in[3];
    const float* flow_prev  = (const float*)d_in[4];
    const float* flow_next  = (const float*)d_in[5];
    const float* off_w[2][4];
    const float* off_b[2][4];
    for (int br = 0; br < 2; br++)
        for (int j = 0; j < 4; j++) {
            off_w[br][j] = (const float*)d_in[6 + br * 8 + 2 * j];
            off_b[br][j] = (const float*)d_in[6 + br * 8 + 2 * j + 1];
        }
    const float* dcn_w[2] = {(const float*)d_in[22], (const float*)d_in[24]};
    const float* dcn_b[2] = {(const float*)d_in[23], (const float*)d_in[25]};
    const float* fus_w = (const float*)d_in[26];
    const float* fus_b = (const float*)d_in[27];
    float* out = (float*)d_out;

    float *bufA, *bufB, *raw, *featT, *fpn, *wre;
    cudaGetSymbolAddress((void**)&bufA,  g_bufA);
    cudaGetSymbolAddress((void**)&bufB,  g_bufB);
    cudaGetSymbolAddress((void**)&raw,   g_raw);
    cudaGetSymbolAddress((void**)&featT, g_featT);
    cudaGetSymbolAddress((void**)&fpn,   g_fpn);
    cudaGetSymbolAddress((void**)&wre,   g_wre);

    float* bufA1 = bufA + (size_t)64 * HWP;
    float* bufB1 = bufB + (size_t)64 * HWP;
    float* raw1  = raw  + (size_t)216 * HWP;

    const dim3 cb(32, 8);
    const dim3 cgB64 (WW / 32, HH / 32, 16);   // 2 branches x 8 chunks of 8
    const dim3 cgB216(WW / 32, HH / 32, 54);   // 2 branches x 27 chunks of 8 (exact)
    const dim3 cgFus (WW / 32, HH / 32, 8);    // fusion: 1 "branch", 8 chunks
    const dim3 mg(WW / 32, HH / 8, 2);

    // conv stage 0..2 (leaky relu), both branches batched
    conv3x3_kernel<<<cgB64, cb>>>(extra_prev, extra_next,
                                  off_w[0][0], off_w[1][0], off_b[0][0], off_b[1][0],
                                  bufA, bufA1, 128, 64, 8, 1, nullptr, nullptr);
    conv3x3_kernel<<<cgB64, cb>>>(bufA, bufA1,
                                  off_w[0][1], off_w[1][1], off_b[0][1], off_b[1][1],
                                  bufB, bufB1, 64, 64, 8, 1, nullptr, nullptr);
    conv3x3_kernel<<<cgB64, cb>>>(bufB, bufB1,
                                  off_w[0][2], off_w[1][2], off_b[0][2], off_b[1][2],
                                  bufA, bufA1, 64, 64, 8, 1, nullptr, nullptr);
    // conv216 with fused offset/mask activation (+flow add)
    conv3x3_kernel<<<cgB216, cb>>>(bufA, bufA1,
                                   off_w[0][3], off_w[1][3], off_b[0][3], off_b[1][3],
                                   raw, raw1, 64, 216, 27, 2, flow_prev, flow_next);
    // feature transpose + dcn weight reorder
    transpose_kernel<<<dim3(HWP / 256, 8, 2), 256>>>(feat_prev, feat_next, featT);
    wreorder_kernel<<<288, 256>>>(dcn_w[0], dcn_w[1], wre);
    // deformable conv, both branches batched
    mdcn_kernel<<<mg, cb>>>(featT, raw, wre, dcn_b[0], dcn_b[1], fpn);
    // fusion conv
    conv3x3_kernel<<<cgFus, cb>>>(fpn, fpn, fus_w, fus_w, fus_b, fus_b,
                                  out, out, 128, 64, 8, 0, nullptr, nullptr);
}

// round 15
// speedup vs baseline: 1.5754x; 1.1581x over previous
#include <cuda_runtime.h>
#include <math.h>

// Problem constants
#define HH 256
#define WW 256
#define HWP (HH*WW)   // 65536

// ---------------- scratch (no allocations allowed) ----------------
__device__ __align__(16) float g_bufA[2 * 64 * HWP];
__device__ __align__(16) float g_bufB[2 * 64 * HWP];
__device__ __align__(16) float g_raw [2 * 216 * HWP];
__device__ __align__(16) float g_featT[2 * 64 * HWP];   // [br][g][pix][8]
__device__ __align__(16) float g_fpn [128 * HWP];       // cat(fp, fn)
__device__ __align__(16) float g_wre [2 * 8 * 9 * 8 * 64]; // [br][g][k][c][o]

// ---------------- packed fp32x2 helpers (Blackwell FFMA2) ----------------
typedef unsigned long long u64;

__device__ __forceinline__ u64 pk2(float a, float b) {
    u64 r; asm("mov.b64 %0, {%1, %2};" : "=l"(r) : "f"(a), "f"(b)); return r;
}
__device__ __forceinline__ float2 upk2(u64 a) {
    float2 r; asm("mov.b64 {%0, %1}, %2;" : "=f"(r.x), "=f"(r.y) : "l"(a)); return r;
}
__device__ __forceinline__ u64 ffma2(u64 a, u64 b, u64 c) {
    u64 d; asm("fma.rn.f32x2 %0, %1, %2, %3;" : "=l"(d) : "l"(a), "l"(b), "l"(c)); return d;
}

// cp.async 4B with zero-fill on invalid
__device__ __forceinline__ void cp4(unsigned int dst, const void* src, int sz) {
    asm volatile("cp.async.ca.shared.global [%0], [%1], 4, %2;"
                 :: "r"(dst), "l"(src), "r"(sz));
}
__device__ __forceinline__ void cp_commit() {
    asm volatile("cp.async.commit_group;");
}

// ---------------- direct 3x3 conv, pad 1, NCHW, branch-batched (R8 form) ----
// 32x32 pixel tile; 256 threads (32,8); each thread: 4 pixel rows x 16 out chans.
// Double-buffered cp.async pipeline over Cin (4 channels per stage).
// act: 0 = none, 1 = leaky relu, 2 = offset/mask activation (+flow).
#define CO_T 16
#define PY 4
#define TILE_ELEMS (4*34*34)   // 4624
#define W_ELEMS (4*9*CO_T)     // 576

__global__ __launch_bounds__(256, 2)
void conv3x3_kernel(const float* __restrict__ in0, const float* __restrict__ in1,
                    const float* __restrict__ wt0, const float* __restrict__ wt1,
                    const float* __restrict__ bs0, const float* __restrict__ bs1,
                    float* __restrict__ out0, float* __restrict__ out1,
                    int Cin, int Cout, int zPerBr, int act,
                    const float* __restrict__ flow0, const float* __restrict__ flow1)
{
    __shared__ __align__(16) float s_in[2][TILE_ELEMS];
    __shared__ __align__(16) float s_w[2][W_ELEMS];

    const int tx = threadIdx.x, ty = threadIdx.y;
    const int tid = ty * 32 + tx;
    const int br  = blockIdx.z / zPerBr;
    const int coz = blockIdx.z - br * zPerBr;
    const int x0p = blockIdx.x * 32, y0p = blockIdx.y * 32;
    const int co0 = coz * CO_T;

    const float* in   = br ? in1 : in0;
    const float* wt   = br ? wt1 : wt0;
    const float* bias = br ? bs1 : bs0;
    float*       out  = br ? out1 : out0;
    const float* flow = br ? flow1 : flow0;

    // per-thread load descriptors (relative to channel 0)
    int goff[19];
#pragma unroll
    for (int j = 0; j < 19; j++) {
        int idx = tid + j * 256;
        goff[j] = -1;
        if (idx < TILE_ELEMS) {
            int ci  = idx / 1156;
            int rem = idx - ci * 1156;
            int r = rem / 34, c = rem - r * 34;
            int gy = y0p + r - 1, gx = x0p + c - 1;
            if (gy >= 0 && gy < HH && gx >= 0 && gx < WW)
                goff[j] = ci * HWP + gy * WW + gx;
        }
    }
    int woff[3];
#pragma unroll
    for (int j = 0; j < 3; j++) {
        int idx = tid + j * 256;
        woff[j] = -1;
        if (idx < W_ELEMS) {
            int ci  = idx / 144;
            int rem = idx - ci * 144;
            int k = rem >> 4, co = rem & 15;
            if (co0 + co < Cout)
                woff[j] = ((co0 + co) * Cin + ci) * 9 + k;
        }
    }

    const unsigned int s_in_base = (unsigned int)__cvta_generic_to_shared(&s_in[0][0]);
    const unsigned int s_w_base  = (unsigned int)__cvta_generic_to_shared(&s_w[0][0]);
    const int nIter = Cin >> 2;

    auto issue = [&](int it, int buf) {
        const float* inb = in + (size_t)(it * 4) * HWP;
        unsigned int sb = s_in_base + (unsigned)buf * (TILE_ELEMS * 4);
#pragma unroll
        for (int j = 0; j < 19; j++) {
            int idx = tid + j * 256;
            if (idx < TILE_ELEMS)
                cp4(sb + idx * 4, goff[j] >= 0 ? (const void*)(inb + goff[j]) : (const void*)inb,
                    goff[j] >= 0 ? 4 : 0);
        }
        const float* wb = wt + (size_t)(it * 4) * 9;
        unsigned int swb = s_w_base + (unsigned)buf * (W_ELEMS * 4);
#pragma unroll
        for (int j = 0; j < 3; j++) {
            int idx = tid + j * 256;
            if (idx < W_ELEMS)
                cp4(swb + idx * 4, woff[j] >= 0 ? (const void*)(wb + woff[j]) : (const void*)wb,
                    woff[j] >= 0 ? 4 : 0);
        }
        cp_commit();
    };

    u64 acc2[PY][CO_T / 2];
#pragma unroll
    for (int p = 0; p < PY; p++)
#pragma unroll
        for (int i = 0; i < CO_T / 2; i++) acc2[p][i] = 0ull;

    issue(0, 0);

#pragma unroll 1
    for (int it = 0; it < nIter; it++) {
        const int buf = it & 1;
        if (it + 1 < nIter) {
            issue(it + 1, buf ^ 1);
            asm volatile("cp.async.wait_group 1;");
        } else {
            asm volatile("cp.async.wait_group 0;");
        }
        __syncthreads();

        const float* si = &s_in[buf][0];
        const float* sw = &s_w[buf][0];
#pragma unroll 1
        for (int ci = 0; ci < 4; ci++) {
#pragma unroll
            for (int k = 0; k < 9; k++) {
                const int dy = k / 3, dx = k - 3 * (k / 3);
                const ulonglong2* wv2 = (const ulonglong2*)&sw[ci * 144 + k * 16];
                ulonglong2 w01 = wv2[0], w23 = wv2[1];
                ulonglong2 w45 = wv2[2], w67 = wv2[3];
#pragma unroll
                for (int p = 0; p < PY; p++) {
                    float vv = si[ci * 1156 + (ty + 8 * p + dy) * 34 + (tx + dx)];
                    u64 vp = pk2(vv, vv);
                    acc2[p][0] = ffma2(w01.x, vp, acc2[p][0]);
                    acc2[p][1] = ffma2(w01.y, vp, acc2[p][1]);
                    acc2[p][2] = ffma2(w23.x, vp, acc2[p][2]);
                    acc2[p][3] = ffma2(w23.y, vp, acc2[p][3]);
                    acc2[p][4] = ffma2(w45.x, vp, acc2[p][4]);
                    acc2[p][5] = ffma2(w45.y, vp, acc2[p][5]);
                    acc2[p][6] = ffma2(w67.x, vp, acc2[p][6]);
                    acc2[p][7] = ffma2(w67.y, vp, acc2[p][7]);
                }
            }
        }
        __syncthreads();
    }

    const int x = x0p + tx;
#pragma unroll
    for (int p = 0; p < PY; p++) {
        const int y = y0p + ty + 8 * p;
        const int pix = y * WW + x;
#pragma unroll
        for (int i = 0; i < CO_T / 2; i++) {
            float2 v2 = upk2(acc2[p][i]);
#pragma unroll
            for (int h = 0; h < 2; h++) {
                int co = co0 + 2 * i + h;
                if (co < Cout) {
                    float r = ((h == 0) ? v2.x : v2.y) + bias[co];
                    if (act == 1) {
                        r = (r >= 0.f) ? r : 0.1f * r;
                    } else if (act == 2) {
                        if (co < 144) {
                            float f = flow[(size_t)((co & 1) ^ 1) * HWP + pix];
                            r = 10.f * tanhf(r) + f;
                        } else {
                            r = 1.f / (1.f + expf(-r));
                        }
                    }
                    out[(size_t)co * HWP + pix] = r;
                }
            }
        }
    }
}

// ---------------- feat NCHW -> [br][g][pix][8] ----------------
__global__ void transpose_kernel(const float* __restrict__ f0, const float* __restrict__ f1,
                                 float* __restrict__ featT)
{
    int pix = blockIdx.x * blockDim.x + threadIdx.x;
    int g = blockIdx.y;
    int br = blockIdx.z;
    if (pix >= HWP) return;
    const float* feat = br ? f1 : f0;
    const float* base = feat + (size_t)g * 8 * HWP + pix;
    float4 a, b;
    a.x = base[0 * HWP]; a.y = base[1 * HWP]; a.z = base[2 * HWP]; a.w = base[3 * HWP];
    b.x = base[4 * HWP]; b.y = base[5 * HWP]; b.z = base[6 * HWP]; b.w = base[7 * HWP];
    float4* dst = (float4*)(featT + (size_t)br * 64 * HWP + ((size_t)g * HWP + pix) * 8);
    dst[0] = a; dst[1] = b;
}

// ---------------- dcn weight reorder: w[o][g*8+c][k] -> wre[br][g][k][c][o] ----------------
__global__ void wreorder_kernel(const float* __restrict__ w0, const float* __restrict__ w1,
                                float* __restrict__ wre)
{
    int i = blockIdx.x * blockDim.x + threadIdx.x;
    if (i >= 2 * 36864) return;
    int br = i >= 36864;
    int l = i - br * 36864;
    const float* w = br ? w1 : w0;
    int o  = l & 63;
    int t  = l >> 6;
    int c  = t & 7;
    int gk = t >> 3;
    int k = gk % 9;
    int g = gk / 9;
    wre[i] = w[((size_t)o * 64 + g * 8 + c) * 9 + k];
}

// ---------------- modulated deformable conv ----------------
// 256 threads (32,8): h = ty>>2 selects output half (32 of 64 outputs),
// pyr = ty&3 selects pixel row; each thread owns 2 pixels (rows y0, y0+4)
// and 32 outputs. Weight LDS amortized over 2 pixels.
__device__ __forceinline__ void mdcn_corner(const float* __restrict__ fb,
                                            int iy, int ix, float wgt, u64* s2)
{
    if (iy >= 0 && iy < HH && ix >= 0 && ix < WW) {
        const ulonglong2* p = (const ulonglong2*)(fb + ((size_t)iy * WW + ix) * 8);
        ulonglong2 a = p[0], b = p[1];
        u64 wp = pk2(wgt, wgt);
        s2[0] = ffma2(a.x, wp, s2[0]);
        s2[1] = ffma2(a.y, wp, s2[1]);
        s2[2] = ffma2(b.x, wp, s2[2]);
        s2[3] = ffma2(b.y, wp, s2[3]);
    }
}

// sample one (g,k) tap at pixel (x, yy): bilinear + mask, 8 channels -> s[8]
__device__ __forceinline__ void mdcn_sample(const float* __restrict__ fb,
                                            const float* __restrict__ off,
                                            int ch, int pix, int x, int yy,
                                            int dy, int dx, float* s)
{
    float oy = off[(size_t)(2 * ch) * HWP + pix];
    float ox = off[(size_t)(2 * ch + 1) * HWP + pix];
    float m  = off[(size_t)(144 + ch) * HWP + pix];
    float py = (float)(yy + dy - 1) + oy;
    float px = (float)(x + dx - 1) + ox;
    float y0f = floorf(py), x0f = floorf(px);
    float ly = py - y0f, lx = px - x0f;
    int iy = (int)y0f, ix = (int)x0f;

    u64 s2[4];
#pragma unroll
    for (int c = 0; c < 4; c++) s2[c] = 0ull;
    float w00 = (1.f - ly) * (1.f - lx);
    float w01 = (1.f - ly) * lx;
    float w10 = ly * (1.f - lx);
    float w11 = ly * lx;
    mdcn_corner(fb, iy,     ix,     w00, s2);
    mdcn_corner(fb, iy,     ix + 1, w01, s2);
    mdcn_corner(fb, iy + 1, ix,     w10, s2);
    mdcn_corner(fb, iy + 1, ix + 1, w11, s2);
#pragma unroll
    for (int c = 0; c < 4; c++) {
        float2 v2 = upk2(s2[c]);
        s[2 * c]     = v2.x * m;
        s[2 * c + 1] = v2.y * m;
    }
}

__global__ __launch_bounds__(256, 2)
void mdcn_kernel(const float* __restrict__ featT_all, const float* __restrict__ off_all,
                 const float* __restrict__ wre_all,
                 const float* __restrict__ bias0, const float* __restrict__ bias1,
                 float* __restrict__ out_all)
{
    __shared__ __align__(16) float sw[9 * 8 * 64];   // [k][c][o] for current g

    const int tx = threadIdx.x, ty = threadIdx.y;    // (32,8)
    const int tid = ty * 32 + tx;
    const int br = blockIdx.z;
    const int h   = ty >> 2;          // output half: co in [32h, 32h+32)
    const int pyr = ty & 3;           // pixel row within half-tile
    const int x  = blockIdx.x * 32 + tx;
    const int y0 = blockIdx.y * 8 + pyr;             // rows y0, y0+4
    const int pix0 = y0 * WW + x;
    const int pix1 = pix0 + 4 * WW;

    const float* featT = featT_all + (size_t)br * 64 * HWP;
    const float* off   = off_all   + (size_t)br * 216 * HWP;
    const float* wre   = wre_all   + (size_t)br * 36864;
    const float* bias  = br ? bias1 : bias0;
    float*       out   = out_all   + (size_t)br * 64 * HWP;

    u64 acc2[2][16];                  // [px][co-pair], 32 outputs per thread
#pragma unroll
    for (int p = 0; p < 2; p++)
#pragma unroll
        for (int i = 0; i < 16; i++) acc2[p][i] = 0ull;

#pragma unroll 1
    for (int g = 0; g < 8; g++) {
        __syncthreads();
        for (int i = tid; i < 4608; i += 256) sw[i] = wre[g * 4608 + i];
        __syncthreads();

        const float* fb = featT + (size_t)g * HWP * 8;
#pragma unroll 1
        for (int k = 0; k < 9; k++) {
            const int ch = g * 9 + k;
            const int dy = k / 3, dx = k - 3 * (k / 3);

            float s0[8], s1[8];
            mdcn_sample(fb, off, ch, pix0, x, y0,     dy, dx, s0);
            mdcn_sample(fb, off, ch, pix1, x, y0 + 4, dy, dx, s1);

#pragma unroll
            for (int c = 0; c < 8; c++) {
                u64 p0 = pk2(s0[c], s0[c]);
                u64 p1 = pk2(s1[c], s1[c]);
                const ulonglong2* wp = (const ulonglong2*)&sw[(k * 8 + c) * 64 + 32 * h];
#pragma unroll
                for (int j = 0; j < 8; j++) {
                    ulonglong2 wv = wp[j];
                    acc2[0][2 * j    ] = ffma2(wv.x, p0, acc2[0][2 * j    ]);
                    acc2[0][2 * j + 1] = ffma2(wv.y, p0, acc2[0][2 * j + 1]);
                    acc2[1][2 * j    ] = ffma2(wv.x, p1, acc2[1][2 * j    ]);
                    acc2[1][2 * j + 1] = ffma2(wv.y, p1, acc2[1][2 * j + 1]);
                }
            }
        }
    }

#pragma unroll
    for (int p = 0; p < 2; p++) {
        const int pix = p ? pix1 : pix0;
#pragma unroll
        for (int i = 0; i < 16; i++) {
            float2 v2 = upk2(acc2[p][i]);
            const int co = 32 * h + 2 * i;
            out[(size_t)(co    ) * HWP + pix] = v2.x + bias[co    ];
            out[(size_t)(co + 1) * HWP + pix] = v2.y + bias[co + 1];
        }
    }
}

// ---------------- launch ----------------
extern "C" void kernel_launch(void* const* d_in, const int* in_sizes, int n_in,
                              void* d_out, int out_size)
{
    (void)in_sizes; (void)n_in; (void)out_size;
    const float* feat_prev  = (const float*)d_in[0];
    const float* feat_next  = (const float*)d_in[1];
    const float* extra_prev = (const float*)d_in[2];
    const float* extra_next = (const float*)d_in[3];
    const float* flow_prev  = (const float*)d_in[4];
    const float* flow_next  = (const float*)d_in[5];
    const float* off_w[2][4];
    const float* off_b[2][4];
    for (int br = 0; br < 2; br++)
        for (int j = 0; j < 4; j++) {
            off_w[br][j] = (const float*)d_in[6 + br * 8 + 2 * j];
            off_b[br][j] = (const float*)d_in[6 + br * 8 + 2 * j + 1];
        }
    const float* dcn_w[2] = {(const float*)d_in[22], (const float*)d_in[24]};
    const float* dcn_b[2] = {(const float*)d_in[23], (const float*)d_in[25]};
    const float* fus_w = (const float*)d_in[26];
    const float* fus_b = (const float*)d_in[27];
    float* out = (float*)d_out;

    float *bufA, *bufB, *raw, *featT, *fpn, *wre;
    cudaGetSymbolAddress((void**)&bufA,  g_bufA);
    cudaGetSymbolAddress((void**)&bufB,  g_bufB);
    cudaGetSymbolAddress((void**)&raw,   g_raw);
    cudaGetSymbolAddress((void**)&featT, g_featT);
    cudaGetSymbolAddress((void**)&fpn,   g_fpn);
    cudaGetSymbolAddress((void**)&wre,   g_wre);

    float* bufA1 = bufA + (size_t)64 * HWP;
    float* bufB1 = bufB + (size_t)64 * HWP;
    float* raw1  = raw  + (size_t)216 * HWP;

    const dim3 cb(32, 8);
    const dim3 cgB64 (WW / 32, HH / 32, 8);    // 2 branches x 4 chunks of 16
    const dim3 cgB216(WW / 32, HH / 32, 28);   // 2 branches x 14 chunks of 16
    const dim3 cgFus (WW / 32, HH / 32, 4);    // fusion: 1 "branch", 4 chunks
    const dim3 mg(WW / 32, HH / 8, 2);

    // conv stage 0..2 (leaky relu), both branches batched
    conv3x3_kernel<<<cgB64, cb>>>(extra_prev, extra_next,
                                  off_w[0][0], off_w[1][0], off_b[0][0], off_b[1][0],
                                  bufA, bufA1, 128, 64, 4, 1, nullptr, nullptr);
    conv3x3_kernel<<<cgB64, cb>>>(bufA, bufA1,
                                  off_w[0][1], off_w[1][1], off_b[0][1], off_b[1][1],
                                  bufB, bufB1, 64, 64, 4, 1, nullptr, nullptr);
    conv3x3_kernel<<<cgB64, cb>>>(bufB, bufB1,
                                  off_w[0][2], off_w[1][2], off_b[0][2], off_b[1][2],
                                  bufA, bufA1, 64, 64, 4, 1, nullptr, nullptr);
    // conv216 with fused offset/mask activation (+flow add)
    conv3x3_kernel<<<cgB216, cb>>>(bufA, bufA1,
                                   off_w[0][3], off_w[1][3], off_b[0][3], off_b[1][3],
                                   raw, raw1, 64, 216, 14, 2, flow_prev, flow_next);
    // feature transpose + dcn weight reorder
    transpose_kernel<<<dim3(HWP / 256, 8, 2), 256>>>(feat_prev, feat_next, featT);
    wreorder_kernel<<<288, 256>>>(dcn_w[0], dcn_w[1], wre);
    // deformable conv, both branches batched
    mdcn_kernel<<<mg, cb>>>(featT, raw, wre, dcn_b[0], dcn_b[1], fpn);
    // fusion conv
    conv3x3_kernel<<<cgFus, cb>>>(fpn, fpn, fus_w, fus_w, fus_b, fus_b,
                                  out, out, 128, 64, 4, 0, nullptr, nullptr);
}